// round 9
// baseline (speedup 1.0000x reference)
#include <cuda_runtime.h>
#include <cuda_bf16.h>
#include <math.h>
#include <cstdint>

#define NB 2
#define NS 2048
#define ND 1024
#define NH 16
#define NDH 64
#define NBH (NB*NH)          // 32
#define NTOK (NB*NS)         // 4096
#define NELEM (NTOK*ND)      // 4194304
#define NW (ND*ND)           // 1048576

// fp32 scratch (head-major: [(b*NH+h)*NS + s]*NDH + d)
__device__ float g_Q[NELEM];
__device__ float g_V[NELEM];
__device__ float g_V1[NELEM];
__device__ float g_K1[NELEM];

// Pre-split bf16 operands
__device__ __nv_bfloat16 g_xhi[NELEM], g_xlo[NELEM];
__device__ __nv_bfloat16 g_yhi[NELEM], g_ylo[NELEM];
__device__ __nv_bfloat16 g_wqhi[NW], g_wqlo[NW];
__device__ __nv_bfloat16 g_wvhi[NW], g_wvlo[NW];
__device__ __nv_bfloat16 g_wohi[NW], g_wolo[NW];
// Attention operands (bf16, pre-split; q scaled by 1/8)
__device__ __nv_bfloat16 g_qhi[NELEM], g_qlo[NELEM];
__device__ __nv_bfloat16 g_khi[NELEM], g_klo[NELEM];
__device__ __nv_bfloat16 g_vthi[NELEM], g_vtlo[NELEM];  // [bh][d][s]

// ===========================================================================
// helpers
// ===========================================================================
__device__ __forceinline__ uint32_t smem_u32(const void* p) {
    uint32_t a;
    asm("{ .reg .u64 t; cvta.to.shared.u64 t, %1; cvt.u32.u64 %0, t; }"
        : "=r"(a) : "l"(p));
    return a;
}
__device__ __forceinline__ void ldsm4(uint32_t r[4], uint32_t addr) {
    asm volatile("ldmatrix.sync.aligned.m8n8.x4.shared.b16 {%0,%1,%2,%3}, [%4];"
                 : "=r"(r[0]), "=r"(r[1]), "=r"(r[2]), "=r"(r[3]) : "r"(addr));
}
__device__ __forceinline__ void mma_bf16(float d[4], const uint32_t a[4],
                                         const uint32_t b[2]) {
    asm volatile(
        "mma.sync.aligned.m16n8k16.row.col.f32.bf16.bf16.f32 "
        "{%0,%1,%2,%3}, {%4,%5,%6,%7}, {%8,%9}, {%0,%1,%2,%3};"
        : "+f"(d[0]), "+f"(d[1]), "+f"(d[2]), "+f"(d[3])
        : "r"(a[0]), "r"(a[1]), "r"(a[2]), "r"(a[3]), "r"(b[0]), "r"(b[1]));
}
__device__ __forceinline__ void cp_async16(uint32_t saddr, const void* g) {
    asm volatile("cp.async.cg.shared.global [%0], [%1], 16;"
                 :: "r"(saddr), "l"(g));
}
__device__ __forceinline__ void cp_commit() {
    asm volatile("cp.async.commit_group;" ::: "memory");
}
__device__ __forceinline__ void cp_wait0() {
    asm volatile("cp.async.wait_group 0;" ::: "memory");
}
__device__ __forceinline__ void cp_wait1() {
    asm volatile("cp.async.wait_group 1;" ::: "memory");
}
__device__ __forceinline__ void split4(float4 v, uint2& hi, uint2& lo) {
    __nv_bfloat16 hx = __float2bfloat16_rn(v.x);
    __nv_bfloat16 hy = __float2bfloat16_rn(v.y);
    __nv_bfloat16 hz = __float2bfloat16_rn(v.z);
    __nv_bfloat16 hw = __float2bfloat16_rn(v.w);
    hi.x = (uint32_t)__bfloat16_as_ushort(hx) | ((uint32_t)__bfloat16_as_ushort(hy) << 16);
    hi.y = (uint32_t)__bfloat16_as_ushort(hz) | ((uint32_t)__bfloat16_as_ushort(hw) << 16);
    __nv_bfloat16 lx = __float2bfloat16_rn(v.x - __bfloat162float(hx));
    __nv_bfloat16 ly = __float2bfloat16_rn(v.y - __bfloat162float(hy));
    __nv_bfloat16 lz = __float2bfloat16_rn(v.z - __bfloat162float(hz));
    __nv_bfloat16 lw = __float2bfloat16_rn(v.w - __bfloat162float(hw));
    lo.x = (uint32_t)__bfloat16_as_ushort(lx) | ((uint32_t)__bfloat16_as_ushort(ly) << 16);
    lo.y = (uint32_t)__bfloat16_as_ushort(lz) | ((uint32_t)__bfloat16_as_ushort(lw) << 16);
}
__device__ __forceinline__ void split2_pack(float a, float b,
                                            uint32_t& hi, uint32_t& lo) {
    __nv_bfloat16 ha = __float2bfloat16_rn(a);
    __nv_bfloat16 hb = __float2bfloat16_rn(b);
    hi = (uint32_t)__bfloat16_as_ushort(ha) | ((uint32_t)__bfloat16_as_ushort(hb) << 16);
    __nv_bfloat16 la = __float2bfloat16_rn(a - __bfloat162float(ha));
    __nv_bfloat16 lb = __float2bfloat16_rn(b - __bfloat162float(hb));
    lo = (uint32_t)__bfloat16_as_ushort(la) | ((uint32_t)__bfloat16_as_ushort(lb) << 16);
}
// FFMA-only exp. Valid for x <= ~0; ~2e-6 rel err.
__device__ __forceinline__ float fast_exp(float x) {
    float y = fmaxf(x * 1.4426950408889634f, -126.0f);
    float z = y + 12582912.0f;
    int   n = __float_as_int(z) - 0x4B400000;
    float r = y - (z - 12582912.0f);
    float p = 1.3333558146e-3f;
    p = fmaf(p, r, 9.6181291076e-3f);
    p = fmaf(p, r, 5.5504108664e-2f);
    p = fmaf(p, r, 2.4022650695e-1f);
    p = fmaf(p, r, 6.9314718056e-1f);
    p = fmaf(p, r, 1.0f);
    return p * __int_as_float((n + 127) << 23);
}

// ===========================================================================
// Pre-split: fp32 -> bf16 hi/lo global arrays. which: 0=x 1=y 2=wq 3=wv 4=wo
// ===========================================================================
__global__ __launch_bounds__(256) void presplit_kernel(const float* __restrict__ src,
                                                       int which)
{
    __nv_bfloat16 *hi, *lo;
    switch (which) {
        case 0: hi = g_xhi;  lo = g_xlo;  break;
        case 1: hi = g_yhi;  lo = g_ylo;  break;
        case 2: hi = g_wqhi; lo = g_wqlo; break;
        case 3: hi = g_wvhi; lo = g_wvlo; break;
        default:hi = g_wohi; lo = g_wolo; break;
    }
    const int idx = blockIdx.x * 256 + threadIdx.x;
    float4 v = ((const float4*)src)[idx];
    uint2 h, l; split4(v, h, l);
    ((uint2*)hi)[idx] = h;
    ((uint2*)lo)[idx] = l;
}

// ===========================================================================
// GEMM v3: 512 threads / 16 warps, warp tile 16x64, 3-stage cp.async.
// C = A @ W^T, 3-pass bf16 split. Block 128x128, k-step 32.
// stage = Ahi|Alo|Whi|Wlo, each 128 rows x 80B = 10240 B; stage 40960 B.
// ===========================================================================
#define GEMM_SMEM (3*40960)   // 122880

__global__ __launch_bounds__(512) void gemm3_mma_kernel()
{
    extern __shared__ __align__(16) char smg[];

    const __nv_bfloat16 *Ahi, *Alo, *Whi, *Wlo; float* C;
    switch (blockIdx.z) {
        case 0:  Ahi=g_xhi; Alo=g_xlo; Whi=g_wqhi; Wlo=g_wqlo; C=g_Q;  break;
        case 1:  Ahi=g_yhi; Alo=g_ylo; Whi=g_wvhi; Wlo=g_wvlo; C=g_V;  break;
        default: Ahi=g_xhi; Alo=g_xlo; Whi=g_wohi; Wlo=g_wolo; C=g_V1; break;
    }
    const int m0   = blockIdx.y * 128;
    const int n0   = blockIdx.x * 128;
    const int tid  = threadIdx.x;
    const int lane = tid & 31, wid = tid >> 5;
    const int wm   = wid >> 1, wn = wid & 1;      // 8 x 2 warp grid, tile 16x64

    const uint32_t sb0 = smem_u32(smg);
    const uint32_t lrow16 = (uint32_t)(lane & 15);
    const uint32_t lchunk = (uint32_t)(lane >> 4) * 16;

    // cp.async mapping: per array, 128 rows x 4 chunks(16B) = 512 slots
    const int crow = tid >> 2;       // 0..127
    const int cc4  = tid & 3;        // 0..3

    float acc[8][4];
#pragma unroll
    for (int j = 0; j < 8; j++)
#pragma unroll
        for (int r = 0; r < 4; r++) acc[j][r] = 0.f;

    auto issue_chunk = [&](int c) {
        const uint32_t stb = sb0 + (uint32_t)(c % 3) * 40960;
        const uint32_t so  = (uint32_t)(crow * 80 + cc4 * 16);
        const size_t ga = (size_t)(m0 + crow) * ND + c * 32 + cc4 * 8;
        const size_t gw = (size_t)(n0 + crow) * ND + c * 32 + cc4 * 8;
        cp_async16(stb + so,         &Ahi[ga]);
        cp_async16(stb + 10240 + so, &Alo[ga]);
        cp_async16(stb + 20480 + so, &Whi[gw]);
        cp_async16(stb + 30720 + so, &Wlo[gw]);
        cp_commit();
    };

    issue_chunk(0);
    issue_chunk(1);

    for (int c = 0; c < 32; c++) {
        if (c + 2 < 32) cp_wait1(); else cp_wait0();
        __syncthreads();
        if (c + 2 < 32) issue_chunk(c + 2);

        const uint32_t stb = sb0 + (uint32_t)(c % 3) * 40960;
        const uint32_t bAh = stb, bAl = stb + 10240;
        const uint32_t bWh = stb + 20480, bWl = stb + 30720;

#pragma unroll
        for (int ks = 0; ks < 2; ks++) {
            const uint32_t kbb = (uint32_t)ks * 32 + lchunk;
            uint32_t ah[4], al[4], bw[8][2], t[4];
            const uint32_t arow = (uint32_t)(wm * 16) + lrow16;
            ldsm4(ah, bAh + arow * 80 + kbb);
            ldsm4(al, bAl + arow * 80 + kbb);
#pragma unroll
            for (int fb = 0; fb < 4; fb++) {
                uint32_t r = (uint32_t)(wn * 64 + fb * 16) + lrow16;
                ldsm4(t, bWh + r * 80 + kbb);
                bw[2*fb][0]   = t[0]; bw[2*fb][1]   = t[2];
                bw[2*fb+1][0] = t[1]; bw[2*fb+1][1] = t[3];
            }
#pragma unroll
            for (int fn = 0; fn < 8; fn++) mma_bf16(acc[fn], ah, bw[fn]);
#pragma unroll
            for (int fn = 0; fn < 8; fn++) mma_bf16(acc[fn], al, bw[fn]);
#pragma unroll
            for (int fb = 0; fb < 4; fb++) {
                uint32_t r = (uint32_t)(wn * 64 + fb * 16) + lrow16;
                ldsm4(t, bWl + r * 80 + kbb);
                bw[2*fb][0]   = t[0]; bw[2*fb][1]   = t[2];
                bw[2*fb+1][0] = t[1]; bw[2*fb+1][1] = t[3];
            }
#pragma unroll
            for (int fn = 0; fn < 8; fn++) mma_bf16(acc[fn], ah, bw[fn]);
        }
        __syncthreads();
    }

    const int g  = lane >> 2;
    const int t2 = (lane & 3) * 2;
    const int bb = m0 >> 11;
    const int h  = blockIdx.x * 2 + wn;
    float* Cb = C + ((size_t)(bb * NH + h) * NS) * NDH;
    const int s = (m0 & (NS - 1)) + wm * 16 + g;
#pragma unroll
    for (int fn = 0; fn < 8; fn++) {
        const int d = fn * 8 + t2;
        *(float2*)&Cb[(size_t)s * NDH + d]       = make_float2(acc[fn][0], acc[fn][1]);
        *(float2*)&Cb[(size_t)(s + 8) * NDH + d] = make_float2(acc[fn][2], acc[fn][3]);
    }
}

// ---------------------------------------------------------------------------
// RoPE: Q in-place + qhi/qlo (x0.125); k_roped -> k_ret + khi/klo; k1 -> g_K1.
// ---------------------------------------------------------------------------
__global__ __launch_bounds__(256) void rope_kernel(
    const float* __restrict__ y, float* __restrict__ k_ret)
{
    const int idx = blockIdx.x * 256 + threadIdx.x;
    const int i   = idx & 31;
    const int s   = (idx >> 5) & (NS - 1);
    const int bh  = idx >> 16;
    const int b   = bh >> 4, h = bh & 15;

    const float LOG2_THETA = 13.287712379549449f;
    const float freq = exp2f(-(float)i * (LOG2_THETA * (1.0f / 32.0f)));
    float sn, cs;
    sincosf((float)s * freq, &sn, &cs);

    const size_t base = ((size_t)bh * NS + s) * NDH;

    float q1 = g_Q[base + i], q2 = g_Q[base + i + 32];
    float qn1 = q1 * cs - q2 * sn;
    float qn2 = q2 * cs + q1 * sn;
    g_Q[base + i]      = qn1;
    g_Q[base + i + 32] = qn2;
    {
        float a1 = qn1 * 0.125f, a2 = qn2 * 0.125f;
        __nv_bfloat16 h1 = __float2bfloat16_rn(a1);
        __nv_bfloat16 h2 = __float2bfloat16_rn(a2);
        g_qhi[base + i]      = h1;
        g_qhi[base + i + 32] = h2;
        g_qlo[base + i]      = __float2bfloat16_rn(a1 - __bfloat162float(h1));
        g_qlo[base + i + 32] = __float2bfloat16_rn(a2 - __bfloat162float(h2));
    }

    const float* yrow = y + ((size_t)b * NS + s) * ND + h * NDH;
    float u1 = yrow[i], u2 = yrow[i + 32];
    float kr1 = u1 * cs - u2 * sn;
    float kr2 = u2 * cs + u1 * sn;
    k_ret[base + i]      = kr1;
    k_ret[base + i + 32] = kr2;
    {
        __nv_bfloat16 h1 = __float2bfloat16_rn(kr1);
        __nv_bfloat16 h2 = __float2bfloat16_rn(kr2);
        g_khi[base + i]      = h1;
        g_khi[base + i + 32] = h2;
        g_klo[base + i]      = __float2bfloat16_rn(kr1 - __bfloat162float(h1));
        g_klo[base + i + 32] = __float2bfloat16_rn(kr2 - __bfloat162float(h2));
    }
    g_K1[base + i]      = kr1 * cs - kr2 * sn;
    g_K1[base + i + 32] = kr2 * cs + kr1 * sn;
}

// ---------------------------------------------------------------------------
// V transpose + split: g_V [bh][s][d] fp32 -> vthi/vtlo [bh][d][s] bf16.
// ---------------------------------------------------------------------------
__global__ __launch_bounds__(256) void vtrans_kernel()
{
    __shared__ __nv_bfloat16 th[64][72];
    __shared__ __nv_bfloat16 tl[64][72];
    const int bh = blockIdx.y;
    const int s0 = blockIdx.x * 64;
    const int tid = threadIdx.x;

#pragma unroll
    for (int i = 0; i < 4; i++) {
        int idx = tid + i * 256;
        int sr = idx >> 4, c4 = idx & 15;
        float4 v = *(const float4*)&g_V[((size_t)bh * NS + s0 + sr) * NDH + c4 * 4];
        float vals[4] = {v.x, v.y, v.z, v.w};
#pragma unroll
        for (int j = 0; j < 4; j++) {
            int d = c4 * 4 + j;
            __nv_bfloat16 hh = __float2bfloat16_rn(vals[j]);
            th[d][sr] = hh;
            tl[d][sr] = __float2bfloat16_rn(vals[j] - __bfloat162float(hh));
        }
    }
    __syncthreads();

#pragma unroll
    for (int i = 0; i < 4; i++) {
        int idx = tid + i * 256;
        int arr = idx >> 9;
        int j = idx & 511;
        int d = j >> 3, c8 = j & 7;
        uint4 v = arr ? *(uint4*)&tl[d][c8 * 8] : *(uint4*)&th[d][c8 * 8];
        __nv_bfloat16* dst = arr ? g_vtlo : g_vthi;
        *(uint4*)&dst[((size_t)bh * NDH + d) * NS + s0 + c8 * 8] = v;
    }
}

// ===========================================================================
// MMA flash attention v2: 512 threads / 16 warps, 256-row Q tile.
// Q fragments live in registers (loaded once); KV double-buffered via cp.async.
// smem: 2 stages x 36864 (KH+0 KL+9216 VH+18432 VL+27648); Q staged there
// transiently before the pipeline starts.
// ===========================================================================
#define ASTG 36864
#define ATTN_SMEM (2*ASTG)    // 73728

__global__ __launch_bounds__(512) void attn_mma_kernel(float* __restrict__ out)
{
    extern __shared__ __align__(16) char smraw[];

    const int qt  = (NS / 256 - 1) - blockIdx.x;   // heavy tiles first
    const int bh  = blockIdx.y;
    const int tid = threadIdx.x;
    const int lane = tid & 31, wid = tid >> 5;      // 16 warps, each m16
    const int g = lane >> 2, t2 = (lane & 3) * 2;
    const uint32_t lrow16 = (uint32_t)(lane & 15);
    const uint32_t lchunk = (uint32_t)(lane >> 4) * 16;
    const uint32_t sbase = smem_u32(smraw);

    // ---- stage Q (256x64 hi/lo) into smem, then ldsm into registers ----
    const size_t qbase = ((size_t)bh * NS + qt * 256) * NDH;
#pragma unroll
    for (int i = 0; i < 4; i++) {
        int idx = tid + i * 512;          // 2048 slots per array
        int row = idx >> 3, c8 = idx & 7;
        *(uint4*)(smraw + row * 144 + c8 * 16) =
            *(const uint4*)&g_qhi[qbase + row * NDH + c8 * 8];
        *(uint4*)(smraw + ASTG + row * 144 + c8 * 16) =
            *(const uint4*)&g_qlo[qbase + row * NDH + c8 * 8];
    }
    __syncthreads();

    uint32_t qh[4][4], ql[4][4];
    {
        const uint32_t arow = (uint32_t)(wid * 16) + lrow16;
#pragma unroll
        for (int kb = 0; kb < 4; kb++) {
            ldsm4(qh[kb], sbase + arow * 144 + kb * 32 + lchunk);
            ldsm4(ql[kb], sbase + ASTG + arow * 144 + kb * 32 + lchunk);
        }
    }
    __syncthreads();    // Q smem dead; stages reusable

    float m0 = -1e30f, m1 = -1e30f, l0 = 0.f, l1 = 0.f;
    float O[8][4];
#pragma unroll
    for (int fn = 0; fn < 8; fn++)
#pragma unroll
        for (int j = 0; j < 4; j++) O[fn][j] = 0.f;

    const int jt_end = 4 * qt + 3;
    const int srow = tid >> 3, sc8 = tid & 7;      // 64 rows x 8 chunks = 512

    auto issue_tile = [&](int jt, int st) {
        const uint32_t stb = sbase + (uint32_t)st * ASTG;
        const uint32_t so = (uint32_t)(srow * 144 + sc8 * 16);
        const size_t kb = ((size_t)bh * NS + jt * 64 + srow) * NDH + sc8 * 8;
        cp_async16(stb + so,         &g_khi[kb]);
        cp_async16(stb + 9216 + so,  &g_klo[kb]);
        const size_t vb = ((size_t)bh * NDH + srow) * NS + jt * 64 + sc8 * 8;
        cp_async16(stb + 18432 + so, &g_vthi[vb]);
        cp_async16(stb + 27648 + so, &g_vtlo[vb]);
        cp_commit();
    };

    issue_tile(0, 0);

    for (int jt = 0; jt <= jt_end; jt++) {
        cp_wait0();
        __syncthreads();
        if (jt < jt_end) issue_tile(jt + 1, (jt + 1) & 1);

        const uint32_t stb = sbase + (uint32_t)(jt & 1) * ASTG;
        const uint32_t bKH = stb, bKL = stb + 9216;
        const uint32_t bVH = stb + 18432, bVL = stb + 27648;

        // ---- S = Q K^T (3-pass; K-hi frag regs reused for K-lo) ----
        float s[8][4];
#pragma unroll
        for (int fn = 0; fn < 8; fn++)
#pragma unroll
            for (int j = 0; j < 4; j++) s[fn][j] = 0.f;

#pragma unroll
        for (int kb = 0; kb < 4; kb++) {
            uint32_t bf[8][2], tt[4];
#pragma unroll
            for (int fb = 0; fb < 4; fb++) {
                uint32_t r = (uint32_t)(fb * 16) + lrow16;
                ldsm4(tt, bKH + r * 144 + kb * 32 + lchunk);
                bf[2*fb][0]   = tt[0]; bf[2*fb][1]   = tt[2];
                bf[2*fb+1][0] = tt[1]; bf[2*fb+1][1] = tt[3];
            }
#pragma unroll
            for (int fn = 0; fn < 8; fn++) mma_bf16(s[fn], qh[kb], bf[fn]);
#pragma unroll
            for (int fn = 0; fn < 8; fn++) mma_bf16(s[fn], ql[kb], bf[fn]);
#pragma unroll
            for (int fb = 0; fb < 4; fb++) {
                uint32_t r = (uint32_t)(fb * 16) + lrow16;
                ldsm4(tt, bKL + r * 144 + kb * 32 + lchunk);
                bf[2*fb][0]   = tt[0]; bf[2*fb][1]   = tt[2];
                bf[2*fb+1][0] = tt[1]; bf[2*fb+1][1] = tt[3];
            }
#pragma unroll
            for (int fn = 0; fn < 8; fn++) mma_bf16(s[fn], qh[kb], bf[fn]);
        }

        // ---- masking (exact gate: tile's max col > warp's min row) ----
        const int growb = qt * 256 + wid * 16;
        if (jt * 64 + 63 > growb) {
            const int colb = jt * 64 + t2;
#pragma unroll
            for (int fn = 0; fn < 8; fn++) {
                int col = colb + fn * 8;
                if (col     > growb + g)     s[fn][0] = -1e30f;
                if (col + 1 > growb + g)     s[fn][1] = -1e30f;
                if (col     > growb + g + 8) s[fn][2] = -1e30f;
                if (col + 1 > growb + g + 8) s[fn][3] = -1e30f;
            }
        }

        // ---- online softmax ----
        float mx0 = -1e30f, mx1 = -1e30f;
#pragma unroll
        for (int fn = 0; fn < 8; fn++) {
            mx0 = fmaxf(mx0, fmaxf(s[fn][0], s[fn][1]));
            mx1 = fmaxf(mx1, fmaxf(s[fn][2], s[fn][3]));
        }
        mx0 = fmaxf(mx0, __shfl_xor_sync(0xffffffffu, mx0, 1));
        mx0 = fmaxf(mx0, __shfl_xor_sync(0xffffffffu, mx0, 2));
        mx1 = fmaxf(mx1, __shfl_xor_sync(0xffffffffu, mx1, 1));
        mx1 = fmaxf(mx1, __shfl_xor_sync(0xffffffffu, mx1, 2));
        const float mn0 = fmaxf(m0, mx0), mn1 = fmaxf(m1, mx1);
        const float sc0 = fast_exp(m0 - mn0), sc1 = fast_exp(m1 - mn1);

        float ps0 = 0.f, ps1 = 0.f;
#pragma unroll
        for (int fn = 0; fn < 8; fn++) {
            s[fn][0] = fast_exp(s[fn][0] - mn0);
            s[fn][1] = fast_exp(s[fn][1] - mn0);
            s[fn][2] = fast_exp(s[fn][2] - mn1);
            s[fn][3] = fast_exp(s[fn][3] - mn1);
            ps0 += s[fn][0] + s[fn][1];
            ps1 += s[fn][2] + s[fn][3];
        }
        ps0 += __shfl_xor_sync(0xffffffffu, ps0, 1);
        ps0 += __shfl_xor_sync(0xffffffffu, ps0, 2);
        ps1 += __shfl_xor_sync(0xffffffffu, ps1, 1);
        ps1 += __shfl_xor_sync(0xffffffffu, ps1, 2);
        l0 = l0 * sc0 + ps0; m0 = mn0;
        l1 = l1 * sc1 + ps1; m1 = mn1;
#pragma unroll
        for (int fn = 0; fn < 8; fn++) {
            O[fn][0] *= sc0; O[fn][1] *= sc0;
            O[fn][2] *= sc1; O[fn][3] *= sc1;
        }

        // ---- O += P @ V (3-pass; P packed per-kb, V-hi regs reused) ----
#pragma unroll
        for (int kb = 0; kb < 4; kb++) {
            uint32_t pah[4], pal[4];
            split2_pack(s[2*kb][0],   s[2*kb][1],   pah[0], pal[0]);
            split2_pack(s[2*kb][2],   s[2*kb][3],   pah[1], pal[1]);
            split2_pack(s[2*kb+1][0], s[2*kb+1][1], pah[2], pal[2]);
            split2_pack(s[2*kb+1][2], s[2*kb+1][3], pah[3], pal[3]);

            uint32_t bf[8][2], tt[4];
#pragma unroll
            for (int fb = 0; fb < 4; fb++) {
                uint32_t r = (uint32_t)(fb * 16) + lrow16;
                ldsm4(tt, bVH + r * 144 + kb * 32 + lchunk);
                bf[2*fb][0]   = tt[0]; bf[2*fb][1]   = tt[2];
                bf[2*fb+1][0] = tt[1]; bf[2*fb+1][1] = tt[3];
            }
#pragma unroll
            for (int fn = 0; fn < 8; fn++) mma_bf16(O[fn], pah, bf[fn]);
#pragma unroll
            for (int fn = 0; fn < 8; fn++) mma_bf16(O[fn], pal, bf[fn]);
#pragma unroll
            for (int fb = 0; fb < 4; fb++) {
                uint32_t r = (uint32_t)(fb * 16) + lrow16;
                ldsm4(tt, bVL + r * 144 + kb * 32 + lchunk);
                bf[2*fb][0]   = tt[0]; bf[2*fb][1]   = tt[2];
                bf[2*fb+1][0] = tt[1]; bf[2*fb+1][1] = tt[3];
            }
#pragma unroll
            for (int fn = 0; fn < 8; fn++) mma_bf16(O[fn], pah, bf[fn]);
        }
    }

    // ---- diagonal (k1,v1) bank + normalize + store ----
    const int r0 = wid * 16 + g, r1 = r0 + 8;
    const size_t rowbase = ((size_t)bh * NS + qt * 256);
    const float* qr0 = g_Q  + (rowbase + r0) * NDH;
    const float* qr1 = g_Q  + (rowbase + r1) * NDH;
    const float* k10 = g_K1 + (rowbase + r0) * NDH;
    const float* k11 = g_K1 + (rowbase + r1) * NDH;
    const int toff = (lane & 3) * 16;
    float d0 = 0.f, d1 = 0.f;
#pragma unroll
    for (int j = 0; j < 16; j += 4) {
        float4 a0 = *(const float4*)&qr0[toff + j];
        float4 b0 = *(const float4*)&k10[toff + j];
        d0 += a0.x*b0.x + a0.y*b0.y + a0.z*b0.z + a0.w*b0.w;
        float4 a1 = *(const float4*)&qr1[toff + j];
        float4 b1 = *(const float4*)&k11[toff + j];
        d1 += a1.x*b1.x + a1.y*b1.y + a1.z*b1.z + a1.w*b1.w;
    }
    d0 += __shfl_xor_sync(0xffffffffu, d0, 1);
    d0 += __shfl_xor_sync(0xffffffffu, d0, 2);
    d1 += __shfl_xor_sync(0xffffffffu, d1, 1);
    d1 += __shfl_xor_sync(0xffffffffu, d1, 2);
    d0 *= 0.125f; d1 *= 0.125f;

    const float mf0 = fmaxf(m0, d0), mf1 = fmaxf(m1, d1);
    const float fc0 = fast_exp(m0 - mf0), fc1 = fast_exp(m1 - mf1);
    const float p20 = fast_exp(d0 - mf0), p21 = fast_exp(d1 - mf1);
    const float inv0 = 1.0f / (l0 * fc0 + p20);
    const float inv1 = 1.0f / (l1 * fc1 + p21);

    const int b = bh >> 4, h = bh & 15;
    const float* v10 = g_V1 + (rowbase + r0) * NDH;
    const float* v11 = g_V1 + (rowbase + r1) * NDH;
    float* o0 = out + ((size_t)(b * NS) + qt * 256 + r0) * ND + h * NDH;
    float* o1 = out + ((size_t)(b * NS) + qt * 256 + r1) * ND + h * NDH;
#pragma unroll
    for (int fn = 0; fn < 8; fn++) {
        const int col = fn * 8 + t2;
        float2 w0 = *(const float2*)&v10[col];
        float2 w1 = *(const float2*)&v11[col];
        float2 r0o, r1o;
        r0o.x = (O[fn][0] * fc0 + p20 * w0.x) * inv0;
        r0o.y = (O[fn][1] * fc0 + p20 * w0.y) * inv0;
        r1o.x = (O[fn][2] * fc1 + p21 * w1.x) * inv1;
        r1o.y = (O[fn][3] * fc1 + p21 * w1.y) * inv1;
        *(float2*)&o0[col] = r0o;
        *(float2*)&o1[col] = r1o;
    }
}

// ---------------------------------------------------------------------------
extern "C" void kernel_launch(void* const* d_in, const int* in_sizes, int n_in,
                              void* d_out, int out_size)
{
    const float* x  = (const float*)d_in[0];
    const float* y  = (const float*)d_in[1];
    const float* wq = (const float*)d_in[2];
    // d_in[3] = wk is UNUSED by the reference (K = y directly)
    const float* wv = (const float*)d_in[4];
    const float* wo = (const float*)d_in[5];

    float* out   = (float*)d_out;          // (B,S,D)    = 4194304 floats
    float* k_ret = out + NELEM;            // (B,H,S,DH) = 4194304 floats

    cudaFuncSetAttribute(gemm3_mma_kernel,
                         cudaFuncAttributeMaxDynamicSharedMemorySize, GEMM_SMEM);
    cudaFuncSetAttribute(attn_mma_kernel,
                         cudaFuncAttributeMaxDynamicSharedMemorySize, ATTN_SMEM);

    presplit_kernel<<<NELEM / 1024, 256>>>(x, 0);
    presplit_kernel<<<NELEM / 1024, 256>>>(y, 1);
    presplit_kernel<<<NW / 1024, 256>>>(wq, 2);
    presplit_kernel<<<NW / 1024, 256>>>(wv, 3);
    presplit_kernel<<<NW / 1024, 256>>>(wo, 4);

    gemm3_mma_kernel<<<dim3(8, 32, 3), 512, GEMM_SMEM>>>();
    rope_kernel<<<(NBH * NS * 32) / 256, 256>>>(y, k_ret);
    vtrans_kernel<<<dim3(NS / 64, NBH), 256>>>();
    attn_mma_kernel<<<dim3(NS / 256, NBH), 512, ATTN_SMEM>>>(out);
}